// round 12
// baseline (speedup 1.0000x reference)
#include <cuda_runtime.h>

#define BB   64
#define TT   512
#define DD   256
#define HH   256
#define G4   (4*HH)
#define NBLK 128
#define NTHR 256
#define NBG  4      // batch groups (16 batches each)
#define NUG  32     // unit groups (8 units each)
#define BPB  16     // batches per block
#define UPB  8      // units per block
#define SEGP 36     // 32-float k-segment padded to 36 (bank skew: 36%32=4)

// h after each step: g_h[t][b][unit]
__device__ float g_h[TT][BB][HH];
// per-step, per-batch-group arrival counters (target = NUG)
__device__ unsigned g_cnt[TT][NBG];

typedef unsigned long long u64;

// ---------------------------------------------------------------------------
__global__ void init_kernel() {
    int i = blockIdx.x * blockDim.x + threadIdx.x;
    if (i < TT * NBG) ((unsigned*)g_cnt)[i] = 0u;
}

// ---------------------------------------------------------------------------
__device__ __forceinline__ float sigm(float x) {
    x = fminf(fmaxf(x, -30.f), 30.f);
    return 1.0f / (1.0f + __expf(-x));
}
__device__ __forceinline__ float tanh_e(float x) {
    x = fminf(fmaxf(x, -15.f), 15.f);
    float e = __expf(2.0f * x);
    return (e - 1.0f) / (e + 1.0f);
}

// packed fp32x2 FMA (sm_103a FFMA2 — 2x fp32 throughput per issue)
__device__ __forceinline__ u64 ffma2(u64 a, u64 b, u64 c) {
    u64 d;
    asm("fma.rn.f32x2 %0, %1, %2, %3;" : "=l"(d) : "l"(a), "l"(b), "l"(c));
    return d;
}
__device__ __forceinline__ u64 pack2(float lo, float hi) {
    u64 d; asm("mov.b64 %0, {%1, %2};" : "=l"(d) : "f"(lo), "f"(hi)); return d;
}
__device__ __forceinline__ float2 unpack2(u64 v) {
    float lo, hi; asm("mov.b64 {%0, %1}, %2;" : "=f"(lo), "=f"(hi) : "l"(v));
    return make_float2(lo, hi);
}

__device__ __forceinline__ void cp16(void* smem_dst, const void* gsrc) {
    unsigned d = (unsigned)__cvta_generic_to_shared(smem_dst);
    asm volatile("cp.async.cg.shared.global [%0], [%1], 16;" :: "r"(d), "l"(gsrc));
}
__device__ __forceinline__ void cp_commit() { asm volatile("cp.async.commit_group;"); }
__device__ __forceinline__ void cp_wait0()  { asm volatile("cp.async.wait_group 0;"); }

// ---------------------------------------------------------------------------
// Persistent LSTM scan, weights-in-registers, bank-conflict-free operands.
// Block (bg, ug): batches [bg*16,+16), units [ug*8,+8) -> 32 gate columns.
// Thread tid = c*8 + ks : c = gate*8 + u (column), ks = k-segment (32 k each).
// Operand tiles stored as [batch][segment][36]: lane (c,ks) reads banks
// 4*(ks+i)+j -> all 32 banks covered once per warp access (4-way broadcast
// over the c-replicated lanes) => 1 wavefront per LDS.128.
__global__ void __launch_bounds__(NTHR, 1) lstm_scan_kernel(
    const float* __restrict__ x,   // [B,T,D]
    const float* __restrict__ Wi,  // [D,4H]
    const float* __restrict__ Wh,  // [H,4H]
    const float* __restrict__ bias)// [4H]
{
    __shared__ __align__(16) float xs[2][BPB][8][SEGP];  // 2 x 18KB
    __shared__ __align__(16) float hs[BPB][8][SEGP];     // 18KB
    __shared__ __align__(16) float ps[32][BPB];          //  2KB

    const int tid = threadIdx.x;
    const int blk = blockIdx.x;
    const int bg  = blk & (NBG - 1);
    const int ug  = blk >> 2;
    const int c   = tid >> 3;          // column 0..31
    const int ks  = tid & 7;           // k-segment 0..7
    const int gate = c >> 3, uu = c & 7;
    const int gcol = gate * HH + ug * UPB + uu;

    // ---- weights into registers (one time) ----
    u64 wi_r[16], wh_r[16];
    #pragma unroll
    for (int j = 0; j < 16; ++j) {
        int k = ks * 32 + 2 * j;
        wi_r[j] = pack2(Wi[(size_t)k * G4 + gcol], Wi[(size_t)(k + 1) * G4 + gcol]);
        wh_r[j] = pack2(Wh[(size_t)k * G4 + gcol], Wh[(size_t)(k + 1) * G4 + gcol]);
    }
    const float bias_c = bias[gcol];

    // activation-state mapping (threads < 128): one (unit, batch) each
    const int au = tid >> 4;           // unit 0..7
    const int ab = tid & 15;           // batch 0..15
    float cst = 0.f;

    // chunk mapping for 16KB tile staging: 1024 x 16B chunks, 4 per thread
    // chunk -> batch bl = chunk>>6, row-offset off = chunk&63 (off*4 floats)
    // dest segment = off>>3, within-segment 16B slot = off&7

    // ---- prologue: stage x_0 ----
    #pragma unroll
    for (int j = 0; j < 4; ++j) {
        int chunk = tid + j * NTHR;
        int bl = chunk >> 6, off = chunk & 63;
        cp16(&xs[0][bl][off >> 3][(off & 7) * 4],
             x + ((size_t)(bg * BPB + bl) * TT + 0) * DD + off * 4);
    }
    cp_commit(); cp_wait0();
    __syncthreads();

    for (int t = 0; t < TT; ++t) {
        const int cur = t & 1, nxt = cur ^ 1;

        // 1. prefetch x_{t+1} (issued now, committed with the h stage below)
        if (t + 1 < TT) {
            #pragma unroll
            for (int j = 0; j < 4; ++j) {
                int chunk = tid + j * NTHR;
                int bl = chunk >> 6, off = chunk & 63;
                cp16(&xs[nxt][bl][off >> 3][(off & 7) * 4],
                     x + ((size_t)(bg * BPB + bl) * TT + (t + 1)) * DD + off * 4);
            }
        }

        // 2. x-phase: acc[b] += x_t[b,k] * Wi[k,col]   (16 independent chains)
        u64 acc[BPB];
        #pragma unroll
        for (int b = 0; b < BPB; ++b) acc[b] = 0ull;
        #pragma unroll
        for (int b = 0; b < BPB; ++b) {
            const ulonglong2* xr = (const ulonglong2*)&xs[cur][b][ks][0];
            #pragma unroll
            for (int i = 0; i < 8; ++i) {
                ulonglong2 xv = xr[i];
                acc[b] = ffma2(wi_r[2 * i],     xv.x, acc[b]);
                acc[b] = ffma2(wi_r[2 * i + 1], xv.y, acc[b]);
            }
        }

        if (t > 0) {
            // 3. wait for all unit-groups of this batch-group at t-1
            if (tid == 0) {
                volatile unsigned* f = &g_cnt[t - 1][bg];
                while (*f < (unsigned)NUG) { }
                __threadfence();               // acquire
            }
            __syncthreads();

            // 4. stage h_{t-1} tile (16KB) + retire x prefetch
            const float* hsrc = &g_h[t - 1][bg * BPB][0];
            #pragma unroll
            for (int j = 0; j < 4; ++j) {
                int chunk = tid + j * NTHR;
                int bl = chunk >> 6, off = chunk & 63;
                cp16(&hs[bl][off >> 3][(off & 7) * 4], hsrc + chunk * 16 / 4);
            }
            cp_commit(); cp_wait0();
            __syncthreads();

            // 5. h-phase: acc[b] += h_{t-1}[b,k] * Wh[k,col]
            #pragma unroll
            for (int b = 0; b < BPB; ++b) {
                const ulonglong2* hr = (const ulonglong2*)&hs[b][ks][0];
                #pragma unroll
                for (int i = 0; i < 8; ++i) {
                    ulonglong2 hv = hr[i];
                    acc[b] = ffma2(wh_r[2 * i],     hv.x, acc[b]);
                    acc[b] = ffma2(wh_r[2 * i + 1], hv.y, acc[b]);
                }
            }
        } else {
            cp_commit(); cp_wait0();           // retire x_1 prefetch group
            __syncthreads();
        }

        // 6. reduce over the 8 k-segments (8 consecutive lanes share a column)
        float4 s[4];
        #pragma unroll
        for (int q = 0; q < BPB; ++q) {
            float2 p = unpack2(acc[q]);
            float v = p.x + p.y;
            v += __shfl_xor_sync(0xffffffffu, v, 1);
            v += __shfl_xor_sync(0xffffffffu, v, 2);
            v += __shfl_xor_sync(0xffffffffu, v, 4);
            ((float*)s)[q] = v + bias_c;
        }
        if (ks == 0) {
            float4* pr = (float4*)&ps[c][0];
            pr[0] = s[0]; pr[1] = s[1]; pr[2] = s[2]; pr[3] = s[3];
        }
        __syncthreads();

        // 7. activations: thread (u, b) owns one cell state
        if (tid < 128) {
            float gi = ps[     au][ab];
            float gf = ps[ 8 + au][ab];
            float gg = ps[16 + au][ab];
            float go = ps[24 + au][ab];
            cst = sigm(gf) * cst + sigm(gi) * tanh_e(gg);
            float hv = sigm(go) * tanh_e(cst);
            g_h[t][bg * BPB + ab][ug * UPB + au] = hv;
        }
        __syncthreads();

        // 8. publish
        if (tid == 0) {
            __threadfence();                   // release
            atomicAdd(&g_cnt[t][bg], 1u);
        }
    }
}

// ---------------------------------------------------------------------------
// block-level reductions (256 threads)
__device__ __forceinline__ float block_sum(float v, volatile float* red) {
    int lane = threadIdx.x & 31, wid = threadIdx.x >> 5;
    #pragma unroll
    for (int o = 16; o; o >>= 1) v += __shfl_down_sync(0xffffffffu, v, o);
    if (lane == 0) red[wid] = v;
    __syncthreads();
    if (threadIdx.x == 0) {
        float s = 0.f;
        #pragma unroll
        for (int i = 0; i < 8; ++i) s += red[i];
        red[0] = s;
    }
    __syncthreads();
    float r = red[0];
    __syncthreads();
    return r;
}
__device__ __forceinline__ float block_max(float v, volatile float* red) {
    int lane = threadIdx.x & 31, wid = threadIdx.x >> 5;
    #pragma unroll
    for (int o = 16; o; o >>= 1) v = fmaxf(v, __shfl_down_sync(0xffffffffu, v, o));
    if (lane == 0) red[wid] = v;
    __syncthreads();
    if (threadIdx.x == 0) {
        float s = red[0];
        #pragma unroll
        for (int i = 1; i < 8; ++i) s = fmaxf(s, red[i]);
        red[0] = s;
    }
    __syncthreads();
    float r = red[0];
    __syncthreads();
    return r;
}

// ---------------------------------------------------------------------------
// Attention + MLP tail. One block per batch element.
//   scores_t = scale*((q0 Wk^T)·h_t + q0·bk) ; o0 = (Σ attn_t h_t) Wv + bv
__global__ void __launch_bounds__(NTHR) attn_tail_kernel(
    const float* __restrict__ Wq, const float* __restrict__ bq,
    const float* __restrict__ Wk, const float* __restrict__ bk,
    const float* __restrict__ Wv, const float* __restrict__ bv,
    const float* __restrict__ Wo, const float* __restrict__ bo,
    const float* __restrict__ W1, const float* __restrict__ b1,
    const float* __restrict__ W2, const float* __restrict__ b2,
    float* __restrict__ out)
{
    __shared__ float h0[HH], q0[HH], u[HH], hbar[HH], vb[HH], ob[HH];
    __shared__ float sc[TT];
    __shared__ float z[32];
    __shared__ float red[8];
    __shared__ float qbk_s;

    const int b = blockIdx.x;
    const int tid = threadIdx.x;
    const int lane = tid & 31, wid = tid >> 5;

    h0[tid] = g_h[0][b][tid];
    __syncthreads();

    // q0 = h0 @ Wq + bq
    {
        float s = bq[tid];
        #pragma unroll 4
        for (int d = 0; d < HH; ++d) s = fmaf(h0[d], Wq[d * HH + tid], s);
        q0[tid] = s;
    }
    __syncthreads();

    // qbk = q0 . bk
    {
        float p = q0[tid] * bk[tid];
        float s = block_sum(p, red);
        if (tid == 0) qbk_s = s;
    }
    __syncthreads();

    // u = q0 @ Wk^T : warp per output row j
    for (int j = wid; j < HH; j += 8) {
        const float* row = Wk + (size_t)j * HH;
        float acc = 0.f;
        #pragma unroll
        for (int d = lane; d < HH; d += 32) acc = fmaf(q0[d], row[d], acc);
        #pragma unroll
        for (int o = 16; o; o >>= 1) acc += __shfl_down_sync(0xffffffffu, acc, o);
        if (lane == 0) u[j] = acc;
    }
    __syncthreads();

    // scores over all t : warp per t
    const float scale = 0.0625f;   // 1/sqrt(256)
    for (int t = wid; t < TT; t += 8) {
        const float* hr = &g_h[t][b][0];
        float acc = 0.f;
        #pragma unroll
        for (int d = lane; d < HH; d += 32) acc = fmaf(u[d], hr[d], acc);
        #pragma unroll
        for (int o = 16; o; o >>= 1) acc += __shfl_down_sync(0xffffffffu, acc, o);
        if (lane == 0) sc[t] = scale * (acc + qbk_s);
    }
    __syncthreads();

    // softmax over T=512
    {
        float s0 = sc[tid], s1 = sc[tid + 256];
        float M = block_max(fmaxf(s0, s1), red);
        float e0 = __expf(s0 - M), e1 = __expf(s1 - M);
        float S = block_sum(e0 + e1, red);
        float inv = 1.f / S;
        sc[tid] = e0 * inv;
        sc[tid + 256] = e1 * inv;
    }
    __syncthreads();

    // hbar[d] = sum_t attn[t] * h[t][b][d]
    {
        float acc = 0.f;
        #pragma unroll 4
        for (int t = 0; t < TT; ++t) acc = fmaf(sc[t], g_h[t][b][tid], acc);
        hbar[tid] = acc;
    }
    __syncthreads();

    // vb = hbar @ Wv + bv
    {
        float s = bv[tid];
        #pragma unroll 4
        for (int d = 0; d < HH; ++d) s = fmaf(hbar[d], Wv[d * HH + tid], s);
        vb[tid] = s;
    }
    __syncthreads();

    // ob = vb @ Wo + bo
    {
        float s = bo[tid];
        #pragma unroll 4
        for (int d = 0; d < HH; ++d) s = fmaf(vb[d], Wo[d * HH + tid], s);
        ob[tid] = s;
    }
    __syncthreads();

    // z = relu(ob @ W1 + b1)
    if (tid < 32) {
        float s = b1[tid];
        #pragma unroll 4
        for (int d = 0; d < HH; ++d) s = fmaf(ob[d], W1[d * 32 + tid], s);
        z[tid] = fmaxf(s, 0.f);
    }
    __syncthreads();

    // out = z @ W2 + b2
    if (tid < 3) {
        float s = b2[tid];
        #pragma unroll
        for (int d = 0; d < 32; ++d) s = fmaf(z[d], W2[d * 3 + tid], s);
        out[b * 3 + tid] = s;
    }
}

// ---------------------------------------------------------------------------
extern "C" void kernel_launch(void* const* d_in, const int* in_sizes, int n_in,
                              void* d_out, int out_size) {
    const float* x  = (const float*)d_in[0];
    const float* Wi = (const float*)d_in[1];
    const float* Wh = (const float*)d_in[2];
    const float* bg = (const float*)d_in[3];
    const float* Wq = (const float*)d_in[4];
    const float* bq = (const float*)d_in[5];
    const float* Wk = (const float*)d_in[6];
    const float* bk = (const float*)d_in[7];
    const float* Wv = (const float*)d_in[8];
    const float* bv = (const float*)d_in[9];
    const float* Wo = (const float*)d_in[10];
    const float* bo = (const float*)d_in[11];
    const float* W1 = (const float*)d_in[12];
    const float* b1 = (const float*)d_in[13];
    const float* W2 = (const float*)d_in[14];
    const float* b2 = (const float*)d_in[15];
    float* out = (float*)d_out;

    init_kernel<<<8, 256>>>();
    lstm_scan_kernel<<<NBLK, NTHR>>>(x, Wi, Wh, bg);
    attn_tail_kernel<<<BB, NTHR>>>(Wq, bq, Wk, bk, Wv, bv, Wo, bo,
                                   W1, b1, W2, b2, out);
}

// round 15
// speedup vs baseline: 1.0865x; 1.0865x over previous
#include <cuda_runtime.h>

#define BB   64
#define TT   512
#define DD   256
#define HH   256
#define G4   (4*HH)
#define NBLK 128     // scan blocks = NBG*NUG
#define NTHR 256
#define NBG  4       // batch groups (16 batches each)
#define NUG  32      // unit groups (8 units each)
#define TCH  32      // t per GEMM block
#define TCB  (TT/TCH) // 16 GEMM t-chunks

typedef unsigned long long u64;

// h (transposed, for scan staging): g_h2[t][unit][batch]
__device__ float g_h2[TT][HH][BB];
// h (batch-major, for the attention tail): g_h[t][batch][unit]
__device__ float g_h[TT][BB][HH];
// x transposed: g_xT[t][d][b]
__device__ float g_xT[TT][DD][BB];
// xg = x@Wi + b, laid out [t][ug][warp][bg][lane][2]
__device__ float g_xg[TT][NUG][8][NBG][32][2];
// per-step, per-batch-group arrival counters (target = NUG)
__device__ unsigned g_cnt[TT][NBG];

// ---------------------------------------------------------------------------
__global__ void init_kernel() {
    int i = blockIdx.x * blockDim.x + threadIdx.x;
    if (i < TT * NBG) ((unsigned*)g_cnt)[i] = 0u;
}

// ---------------------------------------------------------------------------
__device__ __forceinline__ float sigm(float x) {
    x = fminf(fmaxf(x, -30.f), 30.f);
    return 1.0f / (1.0f + __expf(-x));
}
__device__ __forceinline__ float tanh_e(float x) {
    x = fminf(fmaxf(x, -15.f), 15.f);
    float e = __expf(2.0f * x);
    return (e - 1.0f) / (e + 1.0f);
}

// packed fp32x2 ops (sm_103a FFMA2 path)
__device__ __forceinline__ u64 ffma2(u64 a, u64 b, u64 c) {
    u64 d;
    asm("fma.rn.f32x2 %0, %1, %2, %3;" : "=l"(d) : "l"(a), "l"(b), "l"(c));
    return d;
}
__device__ __forceinline__ u64 add2(u64 a, u64 b) {
    u64 d;
    asm("add.rn.f32x2 %0, %1, %2;" : "=l"(d) : "l"(a), "l"(b));
    return d;
}
__device__ __forceinline__ u64 pack2(float lo, float hi) {
    u64 d; asm("mov.b64 %0, {%1, %2};" : "=l"(d) : "f"(lo), "f"(hi)); return d;
}
__device__ __forceinline__ float2 unpack2(u64 v) {
    float lo, hi; asm("mov.b64 {%0, %1}, %2;" : "=f"(lo), "=f"(hi) : "l"(v));
    return make_float2(lo, hi);
}
__device__ __forceinline__ u64 shfl_xor_u64(u64 x, int d) {
    unsigned lo = (unsigned)x, hi = (unsigned)(x >> 32);
    lo = __shfl_xor_sync(0xffffffffu, lo, d);
    hi = __shfl_xor_sync(0xffffffffu, hi, d);
    return ((u64)hi << 32) | (u64)lo;
}
__device__ __forceinline__ u64 shfl_idx_u64(u64 x, int src) {
    unsigned lo = (unsigned)x, hi = (unsigned)(x >> 32);
    lo = __shfl_sync(0xffffffffu, lo, src);
    hi = __shfl_sync(0xffffffffu, hi, src);
    return ((u64)hi << 32) | (u64)lo;
}

__device__ __forceinline__ void cp16(void* smem_dst, const void* gsrc) {
    unsigned d = (unsigned)__cvta_generic_to_shared(smem_dst);
    asm volatile("cp.async.cg.shared.global [%0], [%1], 16;" :: "r"(d), "l"(gsrc));
}
__device__ __forceinline__ void cp_commit() { asm volatile("cp.async.commit_group;"); }
__device__ __forceinline__ void cp_wait0()  { asm volatile("cp.async.wait_group 0;"); }

// register-halving butterfly step. After steps 16,8,4,2,1 lane l holds the
// full 32-lane sum of value index m = l.
template<int HALF>
__device__ __forceinline__ void reduce_step(u64* v, int lane) {
    const bool hi = (lane & HALF) != 0;
    #pragma unroll
    for (int j = 0; j < HALF; ++j) {
        u64 keep = hi ? v[j + HALF] : v[j];
        u64 send = hi ? v[j] : v[j + HALF];
        u64 recv = shfl_xor_u64(send, HALF);
        v[j] = add2(keep, recv);
    }
}

// ---------------------------------------------------------------------------
// x transpose: x[B][T][D] -> g_xT[t][d][b].  grid (TT, 4), 256 threads.
__global__ void transpose_x_kernel(const float* __restrict__ x) {
    __shared__ float tile[64][65];
    const int t  = blockIdx.x;
    const int dg = blockIdx.y;
    const int b  = threadIdx.x >> 2;      // 0..63
    const int q  = threadIdx.x & 3;       // 0..3

    const float4* src = (const float4*)(x + ((size_t)b * TT + t) * DD + dg * 64 + q * 16);
    #pragma unroll
    for (int r = 0; r < 4; ++r) {
        float4 v = src[r];
        int d = q * 16 + r * 4;
        tile[d][b] = v.x; tile[d + 1][b] = v.y;
        tile[d + 2][b] = v.z; tile[d + 3][b] = v.w;
    }
    __syncthreads();

    const int dl = threadIdx.x >> 2;      // 0..63
    float4* dst = (float4*)(&g_xT[t][dg * 64 + dl][0]);
    #pragma unroll
    for (int r = 0; r < 4; ++r) {
        int c = q * 16 + r * 4;
        dst[q * 4 + r] = make_float4(tile[dl][c], tile[dl][c + 1],
                                     tile[dl][c + 2], tile[dl][c + 3]);
    }
}

// ---------------------------------------------------------------------------
// xg GEMM: g_xg[t][ug][w][bg][l] = (x_t @ Wi + b) for the (bg,ug) slice.
// grid (128, TCB); block (bg,ug) computes TCH timesteps independently.
__global__ void __launch_bounds__(NTHR, 1) xg_gemm_kernel(
    const float* __restrict__ Wi, const float* __restrict__ bias)
{
    __shared__ __align__(16) float xs[2][32][132];

    const int tid = threadIdx.x;
    const int w   = tid >> 5;              // warp = unit 0..7
    const int l   = tid & 31;              // lane = k-owner
    const int bg  = blockIdx.x & (NBG - 1);
    const int ug  = blockIdx.x >> 2;
    const int t0  = blockIdx.y * TCH;

    // Wi slice into registers: wi_r[i*4+g] = dup(Wi[(i*32+l)][g*HH + ug*8 + w])
    u64 wi_r[32];
    #pragma unroll
    for (int i = 0; i < 8; ++i) {
        int k = i * 32 + l;
        #pragma unroll
        for (int g = 0; g < 4; ++g) {
            float wv = Wi[(size_t)k * G4 + g * HH + ug * 8 + w];
            wi_r[i * 4 + g] = pack2(wv, wv);
        }
    }
    const float bv = bias[(l >> 3) * HH + ug * 8 + w];   // gate = l>>3 (m = l)
    const u64 bias2 = pack2(bv, bv);

    // stage t0 into buffer 0: thread stages k-row = tid
    {
        const float* src = &g_xT[t0][tid][bg * 16];
        float* dst = &xs[0][tid & 31][(tid >> 5) * 16];
        cp16(dst, src); cp16(dst + 4, src + 4);
        cp16(dst + 8, src + 8); cp16(dst + 12, src + 12);
        cp_commit(); cp_wait0();
    }
    __syncthreads();

    for (int tt = 0; tt < TCH; ++tt) {
        const int t = t0 + tt;
        const int cur = tt & 1, nxt = cur ^ 1;

        if (tt + 1 < TCH) {
            const float* src = &g_xT[t + 1][tid][bg * 16];
            float* dst = &xs[nxt][tid & 31][(tid >> 5) * 16];
            cp16(dst, src); cp16(dst + 4, src + 4);
            cp16(dst + 8, src + 8); cp16(dst + 12, src + 12);
            cp_commit();
        }

        u64 acc[32];
        #pragma unroll
        for (int m = 0; m < 32; ++m) acc[m] = 0ull;

        #pragma unroll
        for (int i = 0; i < 8; ++i) {
            const ulonglong2* hp = (const ulonglong2*)&xs[cur][l][i * 16];
            ulonglong2 A = hp[0], B = hp[1], C = hp[2], D = hp[3];
            u64 hb[8] = {A.x, A.y, B.x, B.y, C.x, C.y, D.x, D.y};
            #pragma unroll
            for (int g = 0; g < 4; ++g)
                #pragma unroll
                for (int bp = 0; bp < 8; ++bp)
                    acc[g * 8 + bp] = ffma2(wi_r[i * 4 + g], hb[bp], acc[g * 8 + bp]);
        }

        reduce_step<16>(acc, l); reduce_step<8>(acc, l);
        reduce_step<4>(acc, l);  reduce_step<2>(acc, l);
        reduce_step<1>(acc, l);

        u64 res = add2(acc[0], bias2);
        *(u64*)&g_xg[t][ug][w][bg][l][0] = res;

        cp_wait0();
        __syncthreads();
    }
}

// ---------------------------------------------------------------------------
// Persistent LSTM scan (h-recurrence only; xg precomputed).
// Block (bg,ug); warp w = unit ug*8+w; lane l owns k in {i*32+l}.
__global__ void __launch_bounds__(NTHR, 1) lstm_scan_kernel(
    const float* __restrict__ Wh)
{
    __shared__ __align__(16) float hsT[32][132];

    const int tid = threadIdx.x;
    const int w   = tid >> 5;
    const int l   = tid & 31;
    const int bg  = blockIdx.x & (NBG - 1);
    const int ug  = blockIdx.x >> 2;
    const int ugl = ug * 8 + w;

    u64 wh_r[32];
    #pragma unroll
    for (int i = 0; i < 8; ++i) {
        int k = i * 32 + l;
        #pragma unroll
        for (int g = 0; g < 4; ++g) {
            float wv = Wh[(size_t)k * G4 + g * HH + ugl];
            wh_r[i * 4 + g] = pack2(wv, wv);
        }
    }

    u64 cst = 0ull;                        // c-state (2 batches) on lanes l<8

    for (int t = 0; t < TT; ++t) {
        // xg for (m=l): load early, latency hides under spin/stage/compute
        u64 xg_r = *(const u64*)&g_xg[t][ug][w][bg][l][0];

        u64 acc[32];
        #pragma unroll
        for (int m = 0; m < 32; ++m) acc[m] = 0ull;

        if (t > 0) {
            if (tid == 0) {
                volatile unsigned* f = &g_cnt[t - 1][bg];
                while (*f < (unsigned)NUG) { }
                __threadfence();           // acquire
            }
            __syncthreads();

            // stage h_{t-1}: thread stages unit-row k=tid (64B contiguous)
            {
                const float* src = &g_h2[t - 1][tid][bg * 16];
                float* dst = &hsT[tid & 31][(tid >> 5) * 16];
                cp16(dst, src); cp16(dst + 4, src + 4);
                cp16(dst + 8, src + 8); cp16(dst + 12, src + 12);
                cp_commit(); cp_wait0();
            }
            __syncthreads();

            // h-phase: 32 LDS.128 + 256 FFMA2 per lane
            #pragma unroll
            for (int i = 0; i < 8; ++i) {
                const ulonglong2* hp = (const ulonglong2*)&hsT[l][i * 16];
                ulonglong2 A = hp[0], B = hp[1], C = hp[2], D = hp[3];
                u64 hb[8] = {A.x, A.y, B.x, B.y, C.x, C.y, D.x, D.y};
                #pragma unroll
                for (int g = 0; g < 4; ++g)
                    #pragma unroll
                    for (int bp = 0; bp < 8; ++bp)
                        acc[g * 8 + bp] = ffma2(wh_r[i * 4 + g], hb[bp], acc[g * 8 + bp]);
            }
        }

        // k-reduction: lane l ends holding gate-value m = l
        reduce_step<16>(acc, l); reduce_step<8>(acc, l);
        reduce_step<4>(acc, l);  reduce_step<2>(acc, l);
        reduce_step<1>(acc, l);

        u64 gv = add2(acc[0], xg_r);

        // gather f,g,o gates for this bp from lanes bp+8, bp+16, bp+24
        const int bsel = l & 7;
        u64 gf = shfl_idx_u64(gv, bsel + 8);
        u64 gg = shfl_idx_u64(gv, bsel + 16);
        u64 go = shfl_idx_u64(gv, bsel + 24);

        if (l < 8) {                       // lane l = bp, owns gate-i value
            float2 gi2 = unpack2(gv), gf2 = unpack2(gf);
            float2 gg2 = unpack2(gg), go2 = unpack2(go);
            float2 c2  = unpack2(cst);
            c2.x = sigm(gf2.x) * c2.x + sigm(gi2.x) * tanh_e(gg2.x);
            c2.y = sigm(gf2.y) * c2.y + sigm(gi2.y) * tanh_e(gg2.y);
            float h0 = sigm(go2.x) * tanh_e(c2.x);
            float h1 = sigm(go2.y) * tanh_e(c2.y);
            cst = pack2(c2.x, c2.y);

            const int b0 = bg * 16 + 2 * l;
            *(float2*)&g_h2[t][ugl][b0] = make_float2(h0, h1);
            g_h[t][b0][ugl]     = h0;
            g_h[t][b0 + 1][ugl] = h1;
        }
        __syncthreads();
        if (tid == 0) {
            __threadfence();               // release
            atomicAdd(&g_cnt[t][bg], 1u);
        }
    }
}

// ---------------------------------------------------------------------------
// block-level reductions (256 threads)
__device__ __forceinline__ float block_sum(float v, volatile float* red) {
    int lane = threadIdx.x & 31, wid = threadIdx.x >> 5;
    #pragma unroll
    for (int o = 16; o; o >>= 1) v += __shfl_down_sync(0xffffffffu, v, o);
    if (lane == 0) red[wid] = v;
    __syncthreads();
    if (threadIdx.x == 0) {
        float s = 0.f;
        #pragma unroll
        for (int i = 0; i < 8; ++i) s += red[i];
        red[0] = s;
    }
    __syncthreads();
    float r = red[0];
    __syncthreads();
    return r;
}
__device__ __forceinline__ float block_max(float v, volatile float* red) {
    int lane = threadIdx.x & 31, wid = threadIdx.x >> 5;
    #pragma unroll
    for (int o = 16; o; o >>= 1) v = fmaxf(v, __shfl_down_sync(0xffffffffu, v, o));
    if (lane == 0) red[wid] = v;
    __syncthreads();
    if (threadIdx.x == 0) {
        float s = red[0];
        #pragma unroll
        for (int i = 1; i < 8; ++i) s = fmaxf(s, red[i]);
        red[0] = s;
    }
    __syncthreads();
    float r = red[0];
    __syncthreads();
    return r;
}

// ---------------------------------------------------------------------------
// Attention + MLP tail. One block per batch element.
//   scores_t = scale*((q0 Wk^T)·h_t + q0·bk) ; o0 = (Σ attn_t h_t) Wv + bv
__global__ void __launch_bounds__(NTHR) attn_tail_kernel(
    const float* __restrict__ Wq, const float* __restrict__ bq,
    const float* __restrict__ Wk, const float* __restrict__ bk,
    const float* __restrict__ Wv, const float* __restrict__ bv,
    const float* __restrict__ Wo, const float* __restrict__ bo,
    const float* __restrict__ W1, const float* __restrict__ b1,
    const float* __restrict__ W2, const float* __restrict__ b2,
    float* __restrict__ out)
{
    __shared__ float h0[HH], q0[HH], u[HH], hbar[HH], vb[HH], ob[HH];
    __shared__ float sc[TT];
    __shared__ float z[32];
    __shared__ float red[8];
    __shared__ float qbk_s;

    const int b = blockIdx.x;
    const int tid = threadIdx.x;
    const int lane = tid & 31, wid = tid >> 5;

    h0[tid] = g_h[0][b][tid];
    __syncthreads();

    {   // q0 = h0 @ Wq + bq
        float s = bq[tid];
        #pragma unroll 4
        for (int d = 0; d < HH; ++d) s = fmaf(h0[d], Wq[d * HH + tid], s);
        q0[tid] = s;
    }
    __syncthreads();

    {   // qbk = q0 . bk
        float p = q0[tid] * bk[tid];
        float s = block_sum(p, red);
        if (tid == 0) qbk_s = s;
    }
    __syncthreads();

    // u = q0 @ Wk^T : warp per output row j
    for (int j = wid; j < HH; j += 8) {
        const float* row = Wk + (size_t)j * HH;
        float acc = 0.f;
        #pragma unroll
        for (int d = lane; d < HH; d += 32) acc = fmaf(q0[d], row[d], acc);
        #pragma unroll
        for (int o = 16; o; o >>= 1) acc += __shfl_down_sync(0xffffffffu, acc, o);
        if (lane == 0) u[j] = acc;
    }
    __syncthreads();

    // scores over all t : warp per t
    const float scale = 0.0625f;
    for (int t = wid; t < TT; t += 8) {
        const float* hr = &g_h[t][b][0];
        float acc = 0.f;
        #pragma unroll
        for (int d = lane; d < HH; d += 32) acc = fmaf(u[d], hr[d], acc);
        #pragma unroll
        for (int o = 16; o; o >>= 1) acc += __shfl_down_sync(0xffffffffu, acc, o);
        if (lane == 0) sc[t] = scale * (acc + qbk_s);
    }
    __syncthreads();

    {   // softmax over T=512
        float s0 = sc[tid], s1 = sc[tid + 256];
        float M = block_max(fmaxf(s0, s1), red);
        float e0 = __expf(s0 - M), e1 = __expf(s1 - M);
        float S = block_sum(e0 + e1, red);
        float inv = 1.f / S;
        sc[tid] = e0 * inv;
        sc[tid + 256] = e1 * inv;
    }
    __syncthreads();

    {   // hbar[d] = sum_t attn[t] * h[t][b][d]
        float acc = 0.f;
        #pragma unroll 4
        for (int t = 0; t < TT; ++t) acc = fmaf(sc[t], g_h[t][b][tid], acc);
        hbar[tid] = acc;
    }
    __syncthreads();

    {   // vb = hbar @ Wv + bv
        float s = bv[tid];
        #pragma unroll 4
        for (int d = 0; d < HH; ++d) s = fmaf(hbar[d], Wv[d * HH + tid], s);
        vb[tid] = s;
    }
    __syncthreads();

    {   // ob = vb @ Wo + bo
        float s = bo[tid];
        #pragma unroll 4
        for (int d = 0; d < HH; ++d) s = fmaf(vb[d], Wo[d * HH + tid], s);
        ob[tid] = s;
    }
    __syncthreads();

    if (tid < 32) {   // z = relu(ob @ W1 + b1)
        float s = b1[tid];
        #pragma unroll 4
        for (int d = 0; d < HH; ++d) s = fmaf(ob[d], W1[d * 32 + tid], s);
        z[tid] = fmaxf(s, 0.f);
    }
    __syncthreads();

    if (tid < 3) {    // out = z @ W2 + b2
        float s = b2[tid];
        #pragma unroll
        for (int d = 0; d < 32; ++d) s = fmaf(z[d], W2[d * 3 + tid], s);
        out[b * 3 + tid] = s;
    }
}

// ---------------------------------------------------------------------------
extern "C" void kernel_launch(void* const* d_in, const int* in_sizes, int n_in,
                              void* d_out, int out_size) {
    const float* x  = (const float*)d_in[0];
    const float* Wi = (const float*)d_in[1];
    const float* Wh = (const float*)d_in[2];
    const float* bg = (const float*)d_in[3];
    const float* Wq = (const float*)d_in[4];
    const float* bq = (const float*)d_in[5];
    const float* Wk = (const float*)d_in[6];
    const float* bk = (const float*)d_in[7];
    const float* Wv = (const float*)d_in[8];
    const float* bv = (const float*)d_in[9];
    const float* Wo = (const float*)d_in[10];
    const float* bo = (const float*)d_in[11];
    const float* W1 = (const float*)d_in[12];
    const float* b1 = (const float*)d_in[13];
    const float* W2 = (const float*)d_in[14];
    const float* b2 = (const float*)d_in[15];
    float* out = (float*)d_out;

    init_kernel<<<8, 256>>>();
    transpose_x_kernel<<<dim3(TT, 4), 256>>>(x);
    xg_gemm_kernel<<<dim3(NBLK, TCB), NTHR>>>(Wi, bg);
    lstm_scan_kernel<<<NBLK, NTHR>>>(Wh);
    attn_tail_kernel<<<BB, NTHR>>>(Wq, bq, Wk, bk, Wv, bv, Wo, bo,
                                   W1, b1, W2, b2, out);
}

// round 17
// speedup vs baseline: 1.4423x; 1.3274x over previous
#include <cuda_runtime.h>

#define BB   64
#define TT   512
#define DD   256
#define HH   256
#define G4   (4*HH)
#define NBLK 128      // scan blocks = NBG*NUG
#define NTHR 256
#define NBG  4        // batch groups (16 batches each)
#define NUG  32       // unit groups (8 units each)
#define TCH  32       // t per GEMM block
#define TCB  (TT/TCH) // 16 GEMM t-chunks
#define TILE_BYTES 16384

typedef unsigned long long u64;

// h, staging layout: g_h3[t][bg][c][unit][4]  (16KB contiguous per (t,bg))
// element [t][bg][c][u][j] = h_t(batch = bg*16 + 4c + j, unit = u)
__device__ float g_h3[TT][NBG][4][HH][4];
// h batch-major for the attention tail: g_h[t][b][u]
__device__ float g_h[TT][BB][HH];
// x transposed+grouped: g_xT2[t][bg][c][d][4] = x[bg*16+4c+j][t][d]
__device__ float g_xT2[TT][NBG][4][DD][4];
// xg = x@Wi + b : [t][ug][warp][bg][lane][2]
__device__ float g_xg[TT][NUG][8][NBG][32][2];
// per-step, per-batch-group arrival counters (target = NUG)
__device__ unsigned g_cnt[TT][NBG];

// ---------------------------------------------------------------------------
__global__ void init_kernel() {
    int i = blockIdx.x * blockDim.x + threadIdx.x;
    if (i < TT * NBG) ((unsigned*)g_cnt)[i] = 0u;
}

// ---------------------------------------------------------------------------
__device__ __forceinline__ float sigm(float x) {
    x = fminf(fmaxf(x, -30.f), 30.f);
    return 1.0f / (1.0f + __expf(-x));
}
__device__ __forceinline__ float tanh_e(float x) {
    x = fminf(fmaxf(x, -15.f), 15.f);
    float e = __expf(2.0f * x);
    return (e - 1.0f) / (e + 1.0f);
}

// packed fp32x2 ops (sm_103a FFMA2 path)
__device__ __forceinline__ u64 ffma2(u64 a, u64 b, u64 c) {
    u64 d;
    asm("fma.rn.f32x2 %0, %1, %2, %3;" : "=l"(d) : "l"(a), "l"(b), "l"(c));
    return d;
}
__device__ __forceinline__ u64 add2(u64 a, u64 b) {
    u64 d;
    asm("add.rn.f32x2 %0, %1, %2;" : "=l"(d) : "l"(a), "l"(b));
    return d;
}
__device__ __forceinline__ u64 pack2(float lo, float hi) {
    u64 d; asm("mov.b64 %0, {%1, %2};" : "=l"(d) : "f"(lo), "f"(hi)); return d;
}
__device__ __forceinline__ float2 unpack2(u64 v) {
    float lo, hi; asm("mov.b64 {%0, %1}, %2;" : "=f"(lo), "=f"(hi) : "l"(v));
    return make_float2(lo, hi);
}
__device__ __forceinline__ u64 shfl_xor_u64(u64 x, int d) {
    unsigned lo = (unsigned)x, hi = (unsigned)(x >> 32);
    lo = __shfl_xor_sync(0xffffffffu, lo, d);
    hi = __shfl_xor_sync(0xffffffffu, hi, d);
    return ((u64)hi << 32) | (u64)lo;
}
__device__ __forceinline__ u64 shfl_idx_u64(u64 x, int src) {
    unsigned lo = (unsigned)x, hi = (unsigned)(x >> 32);
    lo = __shfl_sync(0xffffffffu, lo, src);
    hi = __shfl_sync(0xffffffffu, hi, src);
    return ((u64)hi << 32) | (u64)lo;
}

// ---- mbarrier + bulk-async helpers -----------------------------------------
__device__ __forceinline__ unsigned smem_u32(const void* p) {
    return (unsigned)__cvta_generic_to_shared(p);
}
__device__ __forceinline__ void mbar_init(u64* m, unsigned count) {
    asm volatile("mbarrier.init.shared.b64 [%0], %1;"
                 :: "r"(smem_u32(m)), "r"(count) : "memory");
}
__device__ __forceinline__ void mbar_expect_tx(u64* m, unsigned bytes) {
    asm volatile("mbarrier.arrive.expect_tx.shared.b64 _, [%0], %1;"
                 :: "r"(smem_u32(m)), "r"(bytes) : "memory");
}
__device__ __forceinline__ void bulk_g2s(void* dst, const void* src,
                                         unsigned bytes, u64* m) {
    asm volatile(
        "cp.async.bulk.shared::cluster.global.mbarrier::complete_tx::bytes "
        "[%0], [%1], %2, [%3];"
        :: "r"(smem_u32(dst)), "l"(src), "r"(bytes), "r"(smem_u32(m))
        : "memory");
}
__device__ __forceinline__ void mbar_wait(u64* m, unsigned parity) {
    asm volatile(
        "{\n\t"
        ".reg .pred P;\n\t"
        "WAIT_%=:\n\t"
        "mbarrier.try_wait.parity.acquire.cta.shared::cta.b64 P, [%0], %1, 0x989680;\n\t"
        "@P bra.uni DONE_%=;\n\t"
        "bra.uni WAIT_%=;\n\t"
        "DONE_%=:\n\t"
        "}"
        :: "r"(smem_u32(m)), "r"(parity) : "memory");
}

// ---- acquire/release flag ops ----------------------------------------------
__device__ __forceinline__ unsigned ld_acq(const unsigned* p) {
    unsigned v;
    asm volatile("ld.global.acquire.gpu.u32 %0, [%1];" : "=r"(v) : "l"(p) : "memory");
    return v;
}
__device__ __forceinline__ void red_rel_add(unsigned* p, unsigned v) {
    asm volatile("red.release.gpu.global.add.u32 [%0], %1;" :: "l"(p), "r"(v) : "memory");
}

// register-halving butterfly step. After steps 16,8,4,2,1 lane l holds the
// full 32-lane sum of value index m = l.
template<int HALF>
__device__ __forceinline__ void reduce_step(u64* v, int lane) {
    const bool hi = (lane & HALF) != 0;
    #pragma unroll
    for (int j = 0; j < HALF; ++j) {
        u64 keep = hi ? v[j + HALF] : v[j];
        u64 send = hi ? v[j] : v[j + HALF];
        u64 recv = shfl_xor_u64(send, HALF);
        v[j] = add2(keep, recv);
    }
}

// ---------------------------------------------------------------------------
// x transpose: x[B][T][D] -> g_xT2[t][bg][c][d][j].  grid TT, 256 threads.
__global__ void transpose_x_kernel(const float* __restrict__ x) {
    __shared__ float tile[64][65];
    const int t = blockIdx.x;

    for (int dc = 0; dc < 4; ++dc) {
        {   // load: thread (b = tid>>2, q = tid&3) reads 16 floats of d
            const int b = threadIdx.x >> 2, q = threadIdx.x & 3;
            const float4* src = (const float4*)(x + ((size_t)b * TT + t) * DD
                                                + dc * 64 + q * 16);
            #pragma unroll
            for (int r = 0; r < 4; ++r) {
                float4 v = src[r];
                int d = q * 16 + r * 4;
                tile[d][b] = v.x; tile[d + 1][b] = v.y;
                tile[d + 2][b] = v.z; tile[d + 3][b] = v.w;
            }
        }
        __syncthreads();
        {   // store: thread (bgq = tid>>6, dl = tid&63) writes coalesced 16B
            const int bgq = threadIdx.x >> 6, dl = threadIdx.x & 63;
            #pragma unroll
            for (int c = 0; c < 4; ++c) {
                int b0 = bgq * 16 + 4 * c;
                float4 w = make_float4(tile[dl][b0], tile[dl][b0 + 1],
                                       tile[dl][b0 + 2], tile[dl][b0 + 3]);
                *(float4*)&g_xT2[t][bgq][c][dc * 64 + dl][0] = w;
            }
        }
        __syncthreads();
    }
}

// ---------------------------------------------------------------------------
// h transpose: g_h3 -> g_h[t][b][u].  grid TT, 256 threads.
__global__ void transpose_h_kernel() {
    __shared__ float tile[64][65];
    const int t = blockIdx.x;

    for (int uc = 0; uc < 4; ++uc) {
        {   // load: thread (bgq = tid>>6, u2 = tid&63), coalesced 16B reads
            const int bgq = threadIdx.x >> 6, u2 = threadIdx.x & 63;
            #pragma unroll
            for (int c = 0; c < 4; ++c) {
                float4 v = *(const float4*)&g_h3[t][bgq][c][uc * 64 + u2][0];
                int b0 = bgq * 16 + 4 * c;
                tile[u2][b0] = v.x; tile[u2][b0 + 1] = v.y;
                tile[u2][b0 + 2] = v.z; tile[u2][b0 + 3] = v.w;
            }
        }
        __syncthreads();
        {   // store: thread (b = tid>>2, q = tid&3) writes g_h[t][b][...]
            const int b = threadIdx.x >> 2, q = threadIdx.x & 3;
            #pragma unroll
            for (int r = 0; r < 4; ++r) {
                int u0 = q * 16 + r * 4;
                float4 w = make_float4(tile[u0][b], tile[u0 + 1][b],
                                       tile[u0 + 2][b], tile[u0 + 3][b]);
                *(float4*)&g_h[t][b][uc * 64 + u0] = w;
            }
        }
        __syncthreads();
    }
}

// ---------------------------------------------------------------------------
// xg GEMM: bulk-staged tiles, weights in registers, butterfly reduce.
// grid (128, TCB); block (bg,ug) computes TCH timesteps independently.
__global__ void __launch_bounds__(NTHR, 1) xg_gemm_kernel(
    const float* __restrict__ Wi, const float* __restrict__ bias)
{
    __shared__ __align__(16) float xs[2][4][DD][4];   // 2 x 16KB
    __shared__ __align__(8)  u64 mbar[2];

    const int tid = threadIdx.x;
    const int w   = tid >> 5;              // warp = unit 0..7
    const int l   = tid & 31;              // lane = k-owner
    const int bg  = blockIdx.x & (NBG - 1);
    const int ug  = blockIdx.x >> 2;
    const int t0  = blockIdx.y * TCH;

    if (tid == 0) { mbar_init(&mbar[0], 1); mbar_init(&mbar[1], 1); }
    __syncthreads();

    // Wi slice into registers: wi_r[i*4+g] = dup(Wi[(i*32+l)][g*HH + ug*8 + w])
    u64 wi_r[32];
    #pragma unroll
    for (int i = 0; i < 8; ++i) {
        int k = i * 32 + l;
        #pragma unroll
        for (int g = 0; g < 4; ++g) {
            float wv = Wi[(size_t)k * G4 + g * HH + ug * 8 + w];
            wi_r[i * 4 + g] = pack2(wv, wv);
        }
    }
    const float bv = bias[(l >> 3) * HH + ug * 8 + w];   // post-reduce m = l
    const u64 bias2 = pack2(bv, bv);

    if (tid == 0) {
        mbar_expect_tx(&mbar[0], TILE_BYTES);
        bulk_g2s(&xs[0][0][0][0], &g_xT2[t0][bg][0][0][0], TILE_BYTES, &mbar[0]);
    }

    for (int tt = 0; tt < TCH; ++tt) {
        const int cur = tt & 1;
        mbar_wait(&mbar[cur], (tt >> 1) & 1);
        __syncthreads();                    // all done reading buf cur^1

        if (tid == 0 && tt + 1 < TCH) {
            mbar_expect_tx(&mbar[cur ^ 1], TILE_BYTES);
            bulk_g2s(&xs[cur ^ 1][0][0][0], &g_xT2[t0 + tt + 1][bg][0][0][0],
                     TILE_BYTES, &mbar[cur ^ 1]);
        }

        u64 acc[32];
        #pragma unroll
        for (int m = 0; m < 32; ++m) acc[m] = 0ull;

        #pragma unroll
        for (int i = 0; i < 8; ++i) {
            #pragma unroll
            for (int c = 0; c < 4; ++c) {
                ulonglong2 hv = *(const ulonglong2*)&xs[cur][c][i * 32 + l][0];
                #pragma unroll
                for (int g = 0; g < 4; ++g) {
                    acc[g * 8 + 2 * c]     = ffma2(wi_r[i * 4 + g], hv.x, acc[g * 8 + 2 * c]);
                    acc[g * 8 + 2 * c + 1] = ffma2(wi_r[i * 4 + g], hv.y, acc[g * 8 + 2 * c + 1]);
                }
            }
        }

        reduce_step<16>(acc, l); reduce_step<8>(acc, l);
        reduce_step<4>(acc, l);  reduce_step<2>(acc, l);
        reduce_step<1>(acc, l);

        u64 res = add2(acc[0], bias2);
        *(u64*)&g_xg[t0 + tt][ug][w][bg][l][0] = res;
    }
}

// ---------------------------------------------------------------------------
// Persistent LSTM scan (h-recurrence only; xg precomputed).
// Block (bg,ug); warp w = unit ug*8+w; lane l owns k in {i*32+l}.
__global__ void __launch_bounds__(NTHR, 1) lstm_scan_kernel(
    const float* __restrict__ Wh)
{
    __shared__ __align__(16) float hsT[4][HH][4];   // 16KB, bulk-staged
    __shared__ __align__(8)  u64 mbar;

    const int tid = threadIdx.x;
    const int w   = tid >> 5;
    const int l   = tid & 31;
    const int bg  = blockIdx.x & (NBG - 1);
    const int ug  = blockIdx.x >> 2;
    const int ugl = ug * 8 + w;

    if (tid == 0) mbar_init(&mbar, 1);

    u64 wh_r[32];
    #pragma unroll
    for (int i = 0; i < 8; ++i) {
        int k = i * 32 + l;
        #pragma unroll
        for (int g = 0; g < 4; ++g) {
            float wv = Wh[(size_t)k * G4 + g * HH + ugl];
            wh_r[i * 4 + g] = pack2(wv, wv);
        }
    }
    __syncthreads();

    u64 cst = 0ull;                         // c-state (2 batches) on lanes l<8

    for (int t = 0; t < TT; ++t) {
        // xg for (m=l): independent load, latency hides under spin/stage
        u64 xg_r = *(const u64*)&g_xg[t][ug][w][bg][l][0];

        u64 acc[32];
        #pragma unroll
        for (int m = 0; m < 32; ++m) acc[m] = 0ull;

        if (t > 0) {
            if (tid == 0) {
                while (ld_acq(&g_cnt[t - 1][bg]) < (unsigned)NUG) { }
                mbar_expect_tx(&mbar, TILE_BYTES);
                bulk_g2s(&hsT[0][0][0], &g_h3[t - 1][bg][0][0][0],
                         TILE_BYTES, &mbar);
            }
            mbar_wait(&mbar, (t - 1) & 1);

            // h-phase: 32 LDS.128 + 256 FFMA2 per lane, conflict-free
            #pragma unroll
            for (int i = 0; i < 8; ++i) {
                #pragma unroll
                for (int c = 0; c < 4; ++c) {
                    ulonglong2 hv = *(const ulonglong2*)&hsT[c][i * 32 + l][0];
                    #pragma unroll
                    for (int g = 0; g < 4; ++g) {
                        acc[g * 8 + 2 * c]     = ffma2(wh_r[i * 4 + g], hv.x, acc[g * 8 + 2 * c]);
                        acc[g * 8 + 2 * c + 1] = ffma2(wh_r[i * 4 + g], hv.y, acc[g * 8 + 2 * c + 1]);
                    }
                }
            }
        }

        // k-reduction: lane l ends holding gate-value m = l
        reduce_step<16>(acc, l); reduce_step<8>(acc, l);
        reduce_step<4>(acc, l);  reduce_step<2>(acc, l);
        reduce_step<1>(acc, l);

        u64 gv = add2(acc[0], xg_r);

        // gather f,g,o gates for this bp from lanes bp+8, bp+16, bp+24
        const int bsel = l & 7;
        u64 gf = shfl_idx_u64(gv, bsel + 8);
        u64 gg = shfl_idx_u64(gv, bsel + 16);
        u64 go = shfl_idx_u64(gv, bsel + 24);

        if (l < 8) {                        // lane l = bp, owns gate-i value
            float2 gi2 = unpack2(gv), gf2 = unpack2(gf);
            float2 gg2 = unpack2(gg), go2 = unpack2(go);
            float2 c2  = unpack2(cst);
            c2.x = sigm(gf2.x) * c2.x + sigm(gi2.x) * tanh_e(gg2.x);
            c2.y = sigm(gf2.y) * c2.y + sigm(gi2.y) * tanh_e(gg2.y);
            float h0 = sigm(go2.x) * tanh_e(c2.x);
            float h1 = sigm(go2.y) * tanh_e(c2.y);
            cst = pack2(c2.x, c2.y);

            // batches (2l, 2l+1) -> c-block l>>1, slot 2*(l&1)
            *(float2*)&g_h3[t][bg][l >> 1][ugl][2 * (l & 1)] = make_float2(h0, h1);
        }
        __syncthreads();                    // stores done block-wide
        if (tid == 0) red_rel_add(&g_cnt[t][bg], 1u);
    }
}

// ---------------------------------------------------------------------------
// block-level reductions (256 threads)
__device__ __forceinline__ float block_sum(float v, volatile float* red) {
    int lane = threadIdx.x & 31, wid = threadIdx.x >> 5;
    #pragma unroll
    for (int o = 16; o; o >>= 1) v += __shfl_down_sync(0xffffffffu, v, o);
    if (lane == 0) red[wid] = v;
    __syncthreads();
    if (threadIdx.x == 0) {
        float s = 0.f;
        #pragma unroll
        for (int i = 0; i < 8; ++i) s += red[i];
        red[0] = s;
    }
    __syncthreads();
    float r = red[0];
    __syncthreads();
    return r;
}
__device__ __forceinline__ float block_max(float v, volatile float* red) {
    int lane = threadIdx.x & 31, wid = threadIdx.x >> 5;
    #pragma unroll
    for (int o = 16; o; o >>= 1) v = fmaxf(v, __shfl_down_sync(0xffffffffu, v, o));
    if (lane == 0) red[wid] = v;
    __syncthreads();
    if (threadIdx.x == 0) {
        float s = red[0];
        #pragma unroll
        for (int i = 1; i < 8; ++i) s = fmaxf(s, red[i]);
        red[0] = s;
    }
    __syncthreads();
    float r = red[0];
    __syncthreads();
    return r;
}

// ---------------------------------------------------------------------------
// Attention + MLP tail. One block per batch element.
//   scores_t = scale*((q0 Wk^T)·h_t + q0·bk) ; o0 = (Σ attn_t h_t) Wv + bv
__global__ void __launch_bounds__(NTHR) attn_tail_kernel(
    const float* __restrict__ Wq, const float* __restrict__ bq,
    const float* __restrict__ Wk, const float* __restrict__ bk,
    const float* __restrict__ Wv, const float* __restrict__ bv,
    const float* __restrict__ Wo, const float* __restrict__ bo,
    const float* __restrict__ W1, const float* __restrict__ b1,
    const float* __restrict__ W2, const float* __restrict__ b2,
    float* __restrict__ out)
{
    __shared__ float h0[HH], q0[HH], u[HH], hbar[HH], vb[HH], ob[HH];
    __shared__ float sc[TT];
    __shared__ float z[32];
    __shared__ float red[8];
    __shared__ float qbk_s;

    const int b = blockIdx.x;
    const int tid = threadIdx.x;
    const int lane = tid & 31, wid = tid >> 5;

    h0[tid] = g_h[0][b][tid];
    __syncthreads();

    {   // q0 = h0 @ Wq + bq
        float s = bq[tid];
        #pragma unroll 4
        for (int d = 0; d < HH; ++d) s = fmaf(h0[d], Wq[d * HH + tid], s);
        q0[tid] = s;
    }
    __syncthreads();

    {   // qbk = q0 . bk
        float p = q0[tid] * bk[tid];
        float s = block_sum(p, red);
        if (tid == 0) qbk_s = s;
    }
    __syncthreads();

    // u = q0 @ Wk^T : warp per output row j
    for (int j = wid; j < HH; j += 8) {
        const float* row = Wk + (size_t)j * HH;
        float acc = 0.f;
        #pragma unroll
        for (int d = lane; d < HH; d += 32) acc = fmaf(q0[d], row[d], acc);
        #pragma unroll
        for (int o = 16; o; o >>= 1) acc += __shfl_down_sync(0xffffffffu, acc, o);
        if (lane == 0) u[j] = acc;
    }
    __syncthreads();

    // scores over all t : warp per t
    const float scale = 0.0625f;
    for (int t = wid; t < TT; t += 8) {
        const float* hr = &g_h[t][b][0];
        float acc = 0.f;
        #pragma unroll
        for (int d = lane; d < HH; d += 32) acc = fmaf(u[d], hr[d], acc);
        #pragma unroll
        for (int o = 16; o; o >>= 1) acc += __shfl_down_sync(0xffffffffu, acc, o);
        if (lane == 0) sc[t] = scale * (acc + qbk_s);
    }
    __syncthreads();

    {   // softmax over T=512
        float s0 = sc[tid], s1 = sc[tid + 256];
        float M = block_max(fmaxf(s0, s1), red);
        float e0 = __expf(s0 - M), e1 = __expf(s1 - M);
        float S = block_sum(e0 + e1, red);
        float inv = 1.f / S;
        sc[tid] = e0 * inv;
        sc[tid + 256] = e1 * inv;
    }
    __syncthreads();

    {   // hbar[d] = sum_t attn[t] * h[t][b][d]
        float acc = 0.f;
        #pragma unroll 4
        for (int t = 0; t < TT; ++t) acc = fmaf(sc[t], g_h[t][b][tid], acc);
        hbar[tid] = acc;
    }
    __syncthreads();

    {   // vb = hbar @ Wv + bv
        float s = bv[tid];
        #pragma unroll 4
        for (int d = 0; d < HH; ++d) s = fmaf(hbar[d], Wv[d * HH + tid], s);
        vb[tid] = s;
    }
    __syncthreads();

    {   // ob = vb @ Wo + bo
        float s = bo[tid];
        #pragma unroll 4
        for (int d = 0; d < HH; ++d) s = fmaf(vb[d], Wo[d * HH + tid], s);
        ob[tid] = s;
    }
    __syncthreads();

    if (tid < 32) {   // z = relu(ob @ W1 + b1)
        float s = b1[tid];
        #pragma unroll 4
        for (int d = 0; d < HH; ++d) s = fmaf(ob[d], W1[d * 32 + tid], s);
        z[tid] = fmaxf(s, 0.f);
    }
    __syncthreads();

    if (tid < 3) {    // out = z @ W2 + b2
        float s = b2[tid];
        #pragma unroll
        for (int d = 0; d < 32; ++d) s = fmaf(z[d], W2[d * 3 + tid], s);
        out[b * 3 + tid] = s;
    }
}

// ---------------------------------------------------------------------------
extern "C" void kernel_launch(void* const* d_in, const int* in_sizes, int n_in,
                              void* d_out, int out_size) {
    const float* x  = (const float*)d_in[0];
    const float* Wi = (const float*)d_in[1];
    const float* Wh = (const float*)d_in[2];
    const float* bg = (const float*)d_in[3];
    const float* Wq = (const float*)d_in[4];
    const float* bq = (const float*)d_in[5];
    const float* Wk = (const float*)d_in[6];
    const float* bk = (const float*)d_in[7];
    const float* Wv = (const float*)d_in[8];
    const float* bv = (const float*)d_in[9];
    const float* Wo = (const float*)d_in[10];
    const float* bo = (const float*)d_in[11];
    const float* W1 = (const float*)d_in[12];
    const float* b1 = (const float*)d_in[13];
    const float* W2 = (const float*)d_in[14];
    const float* b2 = (const float*)d_in[15];
    float* out = (float*)d_out;

    init_kernel<<<8, 256>>>();
    transpose_x_kernel<<<TT, 256>>>(x);
    xg_gemm_kernel<<<dim3(NBLK, TCB), NTHR>>>(Wi, bg);
    lstm_scan_kernel<<<NBLK, NTHR>>>(Wh);
    transpose_h_kernel<<<TT, 256>>>();
    attn_tail_kernel<<<BB, NTHR>>>(Wq, bq, Wk, bk, Wv, bv, Wo, bo,
                                   W1, b1, W2, b2, out);
}